// round 1
// baseline (speedup 1.0000x reference)
#include <cuda_runtime.h>
#include <cfloat>
#include <cstdint>

#define N_ROWS 16384
#define DIM_IN 1024
#define DIM_H  512
#define MEM_M  8192
#define RATE   0.5f
#define JSPLIT 4

// ---------------- scratch (static device globals: alloc-free) ----------------
__device__ float g_p[(size_t)N_ROWS * DIM_H];     // p, then (p - closest) in place
__device__ float g_upd[(size_t)N_ROWS * DIM_H];   // memory_update
__device__ float g_mnorm[MEM_M];                  // ||m_j||^2
__device__ int   g_idx[N_ROWS];                   // argmin indices
__device__ float g_pbest[JSPLIT * N_ROWS];        // per-j-slice best score
__device__ int   g_pj[JSPLIT * N_ROWS];           // per-j-slice best index

// ---------------- fp32 NT GEMM: C[i,j] = sum_k A[i,k]*B[j,k] + bias[j] -------
// block tile 128x128, k-tile 16, 256 threads, 8x8 per-thread micro-tile
template<int K>
__global__ void __launch_bounds__(256)
gemm_nt_bias(const float* __restrict__ A, const float* __restrict__ B,
             const float* __restrict__ bias, float* __restrict__ C, int Hdim)
{
    __shared__ float As[16][132];
    __shared__ float Bs[16][132];
    const int i0  = blockIdx.y * 128;
    const int j0  = blockIdx.x * 128;
    const int tid = threadIdx.x;
    const int tx  = tid & 15;
    const int ty  = tid >> 4;

    float acc[8][8];
#pragma unroll
    for (int r = 0; r < 8; r++)
#pragma unroll
        for (int c = 0; c < 8; c++) acc[r][c] = 0.f;

    for (int k0 = 0; k0 < K; k0 += 16) {
        // 512 float4 loads per tile per operand; 2 per thread
        for (int q = tid; q < 512; q += 256) {
            int row = q >> 2;
            int k4  = (q & 3) << 2;
            float4 va = *reinterpret_cast<const float4*>(&A[(size_t)(i0 + row) * K + k0 + k4]);
            As[k4 + 0][row] = va.x; As[k4 + 1][row] = va.y;
            As[k4 + 2][row] = va.z; As[k4 + 3][row] = va.w;
            float4 vb = *reinterpret_cast<const float4*>(&B[(size_t)(j0 + row) * K + k0 + k4]);
            Bs[k4 + 0][row] = vb.x; Bs[k4 + 1][row] = vb.y;
            Bs[k4 + 2][row] = vb.z; Bs[k4 + 3][row] = vb.w;
        }
        __syncthreads();
#pragma unroll
        for (int k = 0; k < 16; k++) {
            float4 a0 = *reinterpret_cast<const float4*>(&As[k][ty * 8]);
            float4 a1 = *reinterpret_cast<const float4*>(&As[k][ty * 8 + 4]);
            float4 b0 = *reinterpret_cast<const float4*>(&Bs[k][tx * 8]);
            float4 b1 = *reinterpret_cast<const float4*>(&Bs[k][tx * 8 + 4]);
            float a[8] = {a0.x, a0.y, a0.z, a0.w, a1.x, a1.y, a1.z, a1.w};
            float b[8] = {b0.x, b0.y, b0.z, b0.w, b1.x, b1.y, b1.z, b1.w};
#pragma unroll
            for (int r = 0; r < 8; r++)
#pragma unroll
                for (int c = 0; c < 8; c++)
                    acc[r][c] = fmaf(a[r], b[c], acc[r][c]);
        }
        __syncthreads();
    }

#pragma unroll
    for (int r = 0; r < 8; r++) {
        int row = i0 + ty * 8 + r;
        int col = j0 + tx * 8;
        float4 o0, o1;
        o0.x = acc[r][0] + bias[col + 0];
        o0.y = acc[r][1] + bias[col + 1];
        o0.z = acc[r][2] + bias[col + 2];
        o0.w = acc[r][3] + bias[col + 3];
        o1.x = acc[r][4] + bias[col + 4];
        o1.y = acc[r][5] + bias[col + 5];
        o1.z = acc[r][6] + bias[col + 6];
        o1.w = acc[r][7] + bias[col + 7];
        *reinterpret_cast<float4*>(&C[(size_t)row * Hdim + col])     = o0;
        *reinterpret_cast<float4*>(&C[(size_t)row * Hdim + col + 4]) = o1;
    }
}

// ---------------- memory row squared-norms -----------------------------------
__global__ void __launch_bounds__(256)
row_norms(const float* __restrict__ Mem)
{
    int row  = blockIdx.x * 8 + (threadIdx.x >> 5);
    int lane = threadIdx.x & 31;
    const float4* mrow = reinterpret_cast<const float4*>(Mem + (size_t)row * DIM_H);
    float s = 0.f;
#pragma unroll
    for (int t = lane; t < DIM_H / 4; t += 32) {
        float4 v = mrow[t];
        s += v.x * v.x + v.y * v.y + v.z * v.z + v.w * v.w;
    }
#pragma unroll
    for (int o = 16; o; o >>= 1) s += __shfl_xor_sync(0xffffffffu, s, o);
    if (lane == 0) g_mnorm[row] = s;
}

// ---------------- fused distance GEMM + running argmin ------------------------
// score(i,j) = ||m_j||^2 - 2 * p_i . m_j   (||p_i||^2 constant per row, dropped)
__global__ void __launch_bounds__(256)
dist_argmin(const float* __restrict__ P, const float* __restrict__ B)
{
    const int K = DIM_H;
    __shared__ float As[16][132];
    __shared__ float Bs[16][132];
    __shared__ float sb[128][17];
    __shared__ int   sj[128][17];

    const int i0    = blockIdx.x * 128;
    const int jbase = blockIdx.y * (MEM_M / JSPLIT);
    const int tid   = threadIdx.x;
    const int tx    = tid & 15;
    const int ty    = tid >> 4;

    float best[8];
    int   bestj[8];
#pragma unroll
    for (int r = 0; r < 8; r++) { best[r] = FLT_MAX; bestj[r] = 0; }

    for (int jt = 0; jt < (MEM_M / JSPLIT) / 128; jt++) {
        const int j0 = jbase + jt * 128;
        float acc[8][8];
#pragma unroll
        for (int r = 0; r < 8; r++)
#pragma unroll
            for (int c = 0; c < 8; c++) acc[r][c] = 0.f;

        for (int k0 = 0; k0 < K; k0 += 16) {
            for (int q = tid; q < 512; q += 256) {
                int row = q >> 2;
                int k4  = (q & 3) << 2;
                float4 va = *reinterpret_cast<const float4*>(&P[(size_t)(i0 + row) * K + k0 + k4]);
                As[k4 + 0][row] = va.x; As[k4 + 1][row] = va.y;
                As[k4 + 2][row] = va.z; As[k4 + 3][row] = va.w;
                float4 vb = *reinterpret_cast<const float4*>(&B[(size_t)(j0 + row) * K + k0 + k4]);
                Bs[k4 + 0][row] = vb.x; Bs[k4 + 1][row] = vb.y;
                Bs[k4 + 2][row] = vb.z; Bs[k4 + 3][row] = vb.w;
            }
            __syncthreads();
#pragma unroll
            for (int k = 0; k < 16; k++) {
                float4 a0 = *reinterpret_cast<const float4*>(&As[k][ty * 8]);
                float4 a1 = *reinterpret_cast<const float4*>(&As[k][ty * 8 + 4]);
                float4 b0 = *reinterpret_cast<const float4*>(&Bs[k][tx * 8]);
                float4 b1 = *reinterpret_cast<const float4*>(&Bs[k][tx * 8 + 4]);
                float a[8] = {a0.x, a0.y, a0.z, a0.w, a1.x, a1.y, a1.z, a1.w};
                float b[8] = {b0.x, b0.y, b0.z, b0.w, b1.x, b1.y, b1.z, b1.w};
#pragma unroll
                for (int r = 0; r < 8; r++)
#pragma unroll
                    for (int c = 0; c < 8; c++)
                        acc[r][c] = fmaf(a[r], b[c], acc[r][c]);
            }
            __syncthreads();
        }

        // fold this j-tile into running per-row argmin (j strictly increases
        // within a thread -> strict < keeps the earliest index on ties)
#pragma unroll
        for (int c = 0; c < 8; c++) {
            int   j  = j0 + tx * 8 + c;
            float mn = g_mnorm[j];
#pragma unroll
            for (int r = 0; r < 8; r++) {
                float s = fmaf(-2.f, acc[r][c], mn);
                if (s < best[r]) { best[r] = s; bestj[r] = j; }
            }
        }
    }

    // cross-thread reduce over the 16 column-groups per row
#pragma unroll
    for (int r = 0; r < 8; r++) {
        sb[ty * 8 + r][tx] = best[r];
        sj[ty * 8 + r][tx] = bestj[r];
    }
    __syncthreads();
    if (tid < 128) {
        float bb = sb[tid][0];
        int   bj = sj[tid][0];
#pragma unroll
        for (int t = 1; t < 16; t++) {
            float s = sb[tid][t];
            int   j = sj[tid][t];
            if (s < bb || (s == bb && j < bj)) { bb = s; bj = j; }
        }
        g_pbest[blockIdx.y * N_ROWS + i0 + tid] = bb;
        g_pj[blockIdx.y * N_ROWS + i0 + tid]    = bj;
    }
}

__global__ void __launch_bounds__(256)
argmin_merge()
{
    int i = blockIdx.x * 256 + threadIdx.x;
    if (i >= N_ROWS) return;
    float bb = g_pbest[i];
    int   bj = g_pj[i];
#pragma unroll
    for (int s = 1; s < JSPLIT; s++) {
        float v = g_pbest[s * N_ROWS + i];
        int   j = g_pj[s * N_ROWS + i];
        if (v < bb || (v == bb && j < bj)) { bb = v; bj = j; }
    }
    g_idx[i] = bj;
}

// ---------------- gather closest, compute (p - closest) in place --------------
__global__ void __launch_bounds__(256)
gather_sub(const float* __restrict__ Mem, float* __restrict__ closest_out)
{
    size_t e  = (size_t)blockIdx.x * 256 + threadIdx.x;   // over N*H/4
    int    i  = (int)(e >> 7);                            // H/4 = 128
    int    h4 = (int)(e & 127);
    int    j  = g_idx[i];
    float4 m  = reinterpret_cast<const float4*>(Mem)[(size_t)j * (DIM_H / 4) + h4];
    float4* P4 = reinterpret_cast<float4*>(g_p);
    float4  p  = P4[e];
    reinterpret_cast<float4*>(closest_out)[e] = m;
    p.x -= m.x; p.y -= m.y; p.z -= m.z; p.w -= m.w;
    P4[e] = p;
}

// ---------------- scatter-add updates into output memory ----------------------
__global__ void __launch_bounds__(256)
scatter_add(float* __restrict__ out2)
{
    size_t e = (size_t)blockIdx.x * 256 + threadIdx.x;    // over N*H
    int    i = (int)(e >> 9);                             // H = 512
    int    h = (int)(e & 511);
    int    j = g_idx[i];
    atomicAdd(&out2[(size_t)j * DIM_H + h], RATE * g_upd[e]);
}

// ---------------- launch -------------------------------------------------------
extern "C" void kernel_launch(void* const* d_in, const int* in_sizes, int n_in,
                              void* d_out, int out_size)
{
    const float* V   = (const float*)d_in[0];  // [N, DIM_IN]
    const float* Mem = (const float*)d_in[1];  // [M, H]
    const float* Wp  = (const float*)d_in[2];  // [H, DIM_IN]
    const float* bp  = (const float*)d_in[3];  // [H]
    const float* Wu  = (const float*)d_in[4];  // [H, H]
    const float* bu  = (const float*)d_in[5];  // [H]

    float* out         = (float*)d_out;
    float* closest_out = out;                                 // [N, H]
    float* out2        = out + (size_t)N_ROWS * DIM_H;        // [M, H]

    float* p;   cudaGetSymbolAddress((void**)&p,   g_p);
    float* upd; cudaGetSymbolAddress((void**)&upd, g_upd);

    // p = V @ Wp^T + bp
    gemm_nt_bias<DIM_IN><<<dim3(DIM_H / 128, N_ROWS / 128), 256>>>(V, Wp, bp, p, DIM_H);
    // ||m_j||^2
    row_norms<<<MEM_M / 8, 256>>>(Mem);
    // fused distance + argmin (j-split x4), then merge
    dist_argmin<<<dim3(N_ROWS / 128, JSPLIT), 256>>>(p, Mem);
    argmin_merge<<<N_ROWS / 256, 256>>>();
    // closest = Mem[idx]; p <- p - closest
    gather_sub<<<(N_ROWS * (DIM_H / 4)) / 256, 256>>>(Mem, closest_out);
    // upd = (p - closest) @ Wu^T + bu
    gemm_nt_bias<DIM_H><<<dim3(DIM_H / 128, N_ROWS / 128), 256>>>(p, Wu, bu, upd, DIM_H);
    // updated_memory = Mem, then scatter-add RATE*upd at idx
    cudaMemcpyAsync(out2, Mem, (size_t)MEM_M * DIM_H * sizeof(float),
                    cudaMemcpyDeviceToDevice);
    scatter_add<<<(N_ROWS * DIM_H) / 256, 256>>>(out2);
}

// round 2
// speedup vs baseline: 1.0739x; 1.0739x over previous
#include <cuda_runtime.h>
#include <cfloat>
#include <cstdint>

#define N_ROWS 16384
#define DIM_IN 1024
#define DIM_H  512
#define MEM_M  8192
#define RATE   0.5f
#define JSPLIT 4

// ---------------- packed fp32x2 helpers (Blackwell FFMA2) --------------------
__device__ __forceinline__ unsigned long long fma_f32x2(
    unsigned long long a, unsigned long long b, unsigned long long c)
{
    unsigned long long d;
    asm("fma.rn.f32x2 %0, %1, %2, %3;" : "=l"(d) : "l"(a), "l"(b), "l"(c));
    return d;
}
__device__ __forceinline__ unsigned long long bcast_f32x2(float a)
{
    unsigned long long d;
    asm("mov.b64 %0, {%1, %1};" : "=l"(d) : "f"(a));
    return d;
}
__device__ __forceinline__ void unpack_f32x2(unsigned long long v, float& lo, float& hi)
{
    asm("mov.b64 {%0, %1}, %2;" : "=f"(lo), "=f"(hi) : "l"(v));
}

// ---------------- scratch (static device globals: alloc-free) ----------------
__device__ float g_p[(size_t)N_ROWS * DIM_H];     // p, then (p - closest) in place
__device__ float g_upd[(size_t)N_ROWS * DIM_H];   // memory_update
__device__ float g_mnorm[MEM_M];                  // ||m_j||^2
__device__ int   g_idx[N_ROWS];                   // argmin indices
__device__ float g_pbest[JSPLIT * N_ROWS];        // per-j-slice best score
__device__ int   g_pj[JSPLIT * N_ROWS];           // per-j-slice best index

// ============ packed-fp32 micro-kernel core (shared by all GEMMs) ============
// acc2[r][c2] holds (acc[r][2c2], acc[r][2c2+1]) packed.
struct MicroAcc {
    unsigned long long acc2[8][4];
    __device__ __forceinline__ void zero() {
#pragma unroll
        for (int r = 0; r < 8; r++)
#pragma unroll
            for (int c = 0; c < 4; c++) acc2[r][c] = 0ULL;
    }
};

// one k-tile of 16: As/Bs are [16][132] with row-major-132 stride
__device__ __forceinline__ void micro_mma_tile(
    MicroAcc& m, const float (*As)[132], const float (*Bs)[132], int ty, int tx)
{
#pragma unroll
    for (int k = 0; k < 16; k++) {
        float4 a0 = *reinterpret_cast<const float4*>(&As[k][ty * 8]);
        float4 a1 = *reinterpret_cast<const float4*>(&As[k][ty * 8 + 4]);
        // b pairs: column-contiguous -> direct 64-bit packed loads
        ulonglong2 b01 = *reinterpret_cast<const ulonglong2*>(&Bs[k][tx * 8]);
        ulonglong2 b23 = *reinterpret_cast<const ulonglong2*>(&Bs[k][tx * 8 + 4]);
        unsigned long long bb[4] = {b01.x, b01.y, b23.x, b23.y};
        float a[8] = {a0.x, a0.y, a0.z, a0.w, a1.x, a1.y, a1.z, a1.w};
#pragma unroll
        for (int r = 0; r < 8; r++) {
            unsigned long long pa = bcast_f32x2(a[r]);
#pragma unroll
            for (int c = 0; c < 4; c++)
                m.acc2[r][c] = fma_f32x2(pa, bb[c], m.acc2[r][c]);
        }
    }
}

// tile loader: A,B row-major [.,K]; fills As/Bs[k][row]
template<int K>
__device__ __forceinline__ void load_tiles(
    const float* __restrict__ A, const float* __restrict__ B,
    float (*As)[132], float (*Bs)[132], int i0, int j0, int k0, int tid)
{
    for (int q = tid; q < 512; q += 256) {
        int row = q >> 2;
        int k4  = (q & 3) << 2;
        float4 va = *reinterpret_cast<const float4*>(&A[(size_t)(i0 + row) * K + k0 + k4]);
        As[k4 + 0][row] = va.x; As[k4 + 1][row] = va.y;
        As[k4 + 2][row] = va.z; As[k4 + 3][row] = va.w;
        float4 vb = *reinterpret_cast<const float4*>(&B[(size_t)(j0 + row) * K + k0 + k4]);
        Bs[k4 + 0][row] = vb.x; Bs[k4 + 1][row] = vb.y;
        Bs[k4 + 2][row] = vb.z; Bs[k4 + 3][row] = vb.w;
    }
}

// ---------------- fp32 NT GEMM: C[i,j] = sum_k A[i,k]*B[j,k] + bias[j] -------
template<int K>
__global__ void __launch_bounds__(256)
gemm_nt_bias(const float* __restrict__ A, const float* __restrict__ B,
             const float* __restrict__ bias, float* __restrict__ C, int Hdim)
{
    __shared__ float As[16][132];
    __shared__ float Bs[16][132];
    const int i0  = blockIdx.y * 128;
    const int j0  = blockIdx.x * 128;
    const int tid = threadIdx.x;
    const int tx  = tid & 15;
    const int ty  = tid >> 4;

    MicroAcc m;
    m.zero();

    for (int k0 = 0; k0 < K; k0 += 16) {
        load_tiles<K>(A, B, As, Bs, i0, j0, k0, tid);
        __syncthreads();
        micro_mma_tile(m, As, Bs, ty, tx);
        __syncthreads();
    }

#pragma unroll
    for (int r = 0; r < 8; r++) {
        int row = i0 + ty * 8 + r;
        int col = j0 + tx * 8;
        float o[8];
#pragma unroll
        for (int c = 0; c < 4; c++)
            unpack_f32x2(m.acc2[r][c], o[2 * c], o[2 * c + 1]);
        float4 o0, o1;
        o0.x = o[0] + bias[col + 0];
        o0.y = o[1] + bias[col + 1];
        o0.z = o[2] + bias[col + 2];
        o0.w = o[3] + bias[col + 3];
        o1.x = o[4] + bias[col + 4];
        o1.y = o[5] + bias[col + 5];
        o1.z = o[6] + bias[col + 6];
        o1.w = o[7] + bias[col + 7];
        *reinterpret_cast<float4*>(&C[(size_t)row * Hdim + col])     = o0;
        *reinterpret_cast<float4*>(&C[(size_t)row * Hdim + col + 4]) = o1;
    }
}

// ---------------- memory row squared-norms -----------------------------------
__global__ void __launch_bounds__(256)
row_norms(const float* __restrict__ Mem)
{
    int row  = blockIdx.x * 8 + (threadIdx.x >> 5);
    int lane = threadIdx.x & 31;
    const float4* mrow = reinterpret_cast<const float4*>(Mem + (size_t)row * DIM_H);
    float s = 0.f;
#pragma unroll
    for (int t = lane; t < DIM_H / 4; t += 32) {
        float4 v = mrow[t];
        s += v.x * v.x + v.y * v.y + v.z * v.z + v.w * v.w;
    }
#pragma unroll
    for (int o = 16; o; o >>= 1) s += __shfl_xor_sync(0xffffffffu, s, o);
    if (lane == 0) g_mnorm[row] = s;
}

// ---------------- fused distance GEMM + running argmin ------------------------
// score(i,j) = ||m_j||^2 - 2 * p_i . m_j   (||p_i||^2 constant per row, dropped)
__global__ void __launch_bounds__(256)
dist_argmin(const float* __restrict__ P, const float* __restrict__ B)
{
    __shared__ float As[16][132];
    __shared__ float Bs[16][132];
    __shared__ float sb[128][17];
    __shared__ int   sj[128][17];

    const int i0    = blockIdx.x * 128;
    const int jbase = blockIdx.y * (MEM_M / JSPLIT);
    const int tid   = threadIdx.x;
    const int tx    = tid & 15;
    const int ty    = tid >> 4;

    float best[8];
    int   bestj[8];
#pragma unroll
    for (int r = 0; r < 8; r++) { best[r] = FLT_MAX; bestj[r] = 0; }

    for (int jt = 0; jt < (MEM_M / JSPLIT) / 128; jt++) {
        const int j0 = jbase + jt * 128;
        MicroAcc m;
        m.zero();

        for (int k0 = 0; k0 < DIM_H; k0 += 16) {
            load_tiles<DIM_H>(P, B, As, Bs, i0, j0, k0, tid);
            __syncthreads();
            micro_mma_tile(m, As, Bs, ty, tx);
            __syncthreads();
        }

        // fold this j-tile into running per-row argmin (j strictly increases
        // within a thread -> strict < keeps the earliest index on ties)
#pragma unroll
        for (int c = 0; c < 8; c++) {
            int   j  = j0 + tx * 8 + c;
            float mn = g_mnorm[j];
#pragma unroll
            for (int r = 0; r < 8; r++) {
                float lo, hi, v;
                unpack_f32x2(m.acc2[r][c >> 1], lo, hi);
                v = (c & 1) ? hi : lo;
                float s = fmaf(-2.f, v, mn);
                if (s < best[r]) { best[r] = s; bestj[r] = j; }
            }
        }
    }

    // cross-thread reduce over the 16 column-groups per row
#pragma unroll
    for (int r = 0; r < 8; r++) {
        sb[ty * 8 + r][tx] = best[r];
        sj[ty * 8 + r][tx] = bestj[r];
    }
    __syncthreads();
    if (tid < 128) {
        float bb = sb[tid][0];
        int   bj = sj[tid][0];
#pragma unroll
        for (int t = 1; t < 16; t++) {
            float s = sb[tid][t];
            int   j = sj[tid][t];
            if (s < bb || (s == bb && j < bj)) { bb = s; bj = j; }
        }
        g_pbest[blockIdx.y * N_ROWS + i0 + tid] = bb;
        g_pj[blockIdx.y * N_ROWS + i0 + tid]    = bj;
    }
}

__global__ void __launch_bounds__(256)
argmin_merge()
{
    int i = blockIdx.x * 256 + threadIdx.x;
    if (i >= N_ROWS) return;
    float bb = g_pbest[i];
    int   bj = g_pj[i];
#pragma unroll
    for (int s = 1; s < JSPLIT; s++) {
        float v = g_pbest[s * N_ROWS + i];
        int   j = g_pj[s * N_ROWS + i];
        if (v < bb || (v == bb && j < bj)) { bb = v; bj = j; }
    }
    g_idx[i] = bj;
}

// ---------------- gather closest, compute (p - closest) in place --------------
__global__ void __launch_bounds__(256)
gather_sub(const float* __restrict__ Mem, float* __restrict__ closest_out)
{
    size_t e  = (size_t)blockIdx.x * 256 + threadIdx.x;   // over N*H/4
    int    i  = (int)(e >> 7);                            // H/4 = 128
    int    h4 = (int)(e & 127);
    int    j  = g_idx[i];
    float4 m  = reinterpret_cast<const float4*>(Mem)[(size_t)j * (DIM_H / 4) + h4];
    float4* P4 = reinterpret_cast<float4*>(g_p);
    float4  p  = P4[e];
    reinterpret_cast<float4*>(closest_out)[e] = m;
    p.x -= m.x; p.y -= m.y; p.z -= m.z; p.w -= m.w;
    P4[e] = p;
}

// ---------------- scatter-add updates into output memory ----------------------
__global__ void __launch_bounds__(256)
scatter_add(float* __restrict__ out2)
{
    size_t e = (size_t)blockIdx.x * 256 + threadIdx.x;    // over N*H
    int    i = (int)(e >> 9);                             // H = 512
    int    h = (int)(e & 511);
    int    j = g_idx[i];
    atomicAdd(&out2[(size_t)j * DIM_H + h], RATE * g_upd[e]);
}

// ---------------- launch -------------------------------------------------------
extern "C" void kernel_launch(void* const* d_in, const int* in_sizes, int n_in,
                              void* d_out, int out_size)
{
    const float* V   = (const float*)d_in[0];  // [N, DIM_IN]
    const float* Mem = (const float*)d_in[1];  // [M, H]
    const float* Wp  = (const float*)d_in[2];  // [H, DIM_IN]
    const float* bp  = (const float*)d_in[3];  // [H]
    const float* Wu  = (const float*)d_in[4];  // [H, H]
    const float* bu  = (const float*)d_in[5];  // [H]

    float* out         = (float*)d_out;
    float* closest_out = out;                                 // [N, H]
    float* out2        = out + (size_t)N_ROWS * DIM_H;        // [M, H]

    float* p;   cudaGetSymbolAddress((void**)&p,   g_p);
    float* upd; cudaGetSymbolAddress((void**)&upd, g_upd);

    // p = V @ Wp^T + bp
    gemm_nt_bias<DIM_IN><<<dim3(DIM_H / 128, N_ROWS / 128), 256>>>(V, Wp, bp, p, DIM_H);
    // ||m_j||^2
    row_norms<<<MEM_M / 8, 256>>>(Mem);
    // fused distance + argmin (j-split x4), then merge
    dist_argmin<<<dim3(N_ROWS / 128, JSPLIT), 256>>>(p, Mem);
    argmin_merge<<<N_ROWS / 256, 256>>>();
    // closest = Mem[idx]; p <- p - closest
    gather_sub<<<(N_ROWS * (DIM_H / 4)) / 256, 256>>>(Mem, closest_out);
    // upd = (p - closest) @ Wu^T + bu
    gemm_nt_bias<DIM_H><<<dim3(DIM_H / 128, N_ROWS / 128), 256>>>(p, Wu, bu, upd, DIM_H);
    // updated_memory = Mem, then scatter-add RATE*upd at idx
    cudaMemcpyAsync(out2, Mem, (size_t)MEM_M * DIM_H * sizeof(float),
                    cudaMemcpyDeviceToDevice);
    scatter_add<<<(N_ROWS * DIM_H) / 256, 256>>>(out2);
}